// round 8
// baseline (speedup 1.0000x reference)
#include <cuda_runtime.h>
#include <math.h>

// Problem constants
#define BATCH 4096
#define HDIM  256
#define IDIM  32
#define NNODES 127
#define MAXR  (32 * BATCH)   // largest internal-level row count (d=5)

// ---------------- static device scratch (allowed workaround) ----------------
__device__ float d_Hall[(size_t)NNODES * BATCH * HDIM];  // all node hiddens
__device__ float d_g  [(size_t)MAXR * HDIM];             // g, then s
__device__ float d_cs [(size_t)MAXR * HDIM];             // child_sum
__device__ float d_xir[(size_t)MAXR * HDIM];             // x@wir + wir_b + whr_b
__device__ float d_xiz[(size_t)MAXR * HDIM];             // x@wiz + biases, then z
__device__ float d_xin[(size_t)MAXR * HDIM];             // x@win + biases
__device__ float d_scores[2 * MAXR];
__device__ float d_spart[4 * MAXR];                      // score partials [k][y][row]

// ---------------- accurate activations (immune to --use_fast_math) ----------
__device__ __forceinline__ float tanh_acc(float x) {
    const float ax = fabsf(x);
    if (ax < 0.25f) {
        const float x2 = x * x;
        float p = fmaf(x2, 0.021869488f, -0.053968254f);
        p = fmaf(x2, p, 0.13333334f);
        p = fmaf(x2, p, -0.33333334f);
        return fmaf(x2 * x, p, x);
    }
    const float t = __expf(2.0f * ax);
    const float r = 1.0f - 2.0f / (t + 1.0f);
    return copysignf(r, x);
}

__device__ __forceinline__ float sigmoid_acc(float x) {
    const float e = __expf(-fabsf(x));
    const float s = 1.0f / (1.0f + e);
    return x >= 0.0f ? s : e * s;
}

// packed f32x2 helpers (FFMA2 — 2 IEEE fp32 FMAs per instruction)
typedef unsigned long long ull;
__device__ __forceinline__ ull dup2(float a) {
    ull r;
    asm("mov.b64 %0, {%1, %1};" : "=l"(r) : "f"(a));
    return r;
}
__device__ __forceinline__ void fma2(ull& d, ull a, ull b) {
    asm("fma.rn.f32x2 %0, %1, %2, %0;" : "+l"(d) : "l"(a), "l"(b));
}
__device__ __forceinline__ float2 unpack2(ull v) {
    float lo, hi;
    asm("mov.b64 {%0, %1}, %2;" : "=f"(lo), "=f"(hi) : "l"(v));
    return make_float2(lo, hi);
}

// ---------------- GEMM modes ----------------
#define M_SCORES 0
#define M_TANHB  1
#define M_Z      2
#define M_R0     3
#define M_R1     4
#define M_FINAL  5
#define M_OUT    6

// Generic K=256 SGEMM (exact fp32, FFMA2 inner loop), tile 128x128x8,
// 256 threads, 8x8/thread. Pre-duplicated A in smem, double-buffered,
// 1 barrier per k-step, register prefetch. Launch structure = proven R7.
template<int MODE>
__global__ void __launch_bounds__(256, 2)
gemm256(const float* __restrict__ A,
        const float* __restrict__ W,    // N x 256 row-major
        const float* __restrict__ bias,
        float* __restrict__ outp,
        const float* __restrict__ e0,
        const float* __restrict__ e1,
        const float* __restrict__ e2,
        const float* __restrict__ e3,
        float* __restrict__ eout,
        int start, int kchild)
{
    __shared__ __align__(16) float As2[2][8][264];  // duplicated pairs
    __shared__ __align__(16) float Bs [2][8][132];

    const int tid = threadIdx.x;
    const int rowBase = blockIdx.x * 128;
    const int colBase = blockIdx.y * 128;

    const int r  = tid >> 1;
    const int kq = (tid & 1) * 4;
    const int row_g = rowBase + r;

    long arow;
    if (MODE == M_SCORES || MODE == M_R0 || MODE == M_R1) {
        const int jn = row_g >> 12;
        const int b  = row_g & 4095;
        arow = ((long)(2 * (start + jn) + 1 + kchild) << 12) + b;
    } else {
        arow = row_g;
    }
    const float* Ap = A + arow * 256 + kq;
    const float* Wp = W + (long)(colBase + r) * 256 + kq;

    ull acc[8][4];
#pragma unroll
    for (int i = 0; i < 8; i++)
#pragma unroll
        for (int jp = 0; jp < 4; jp++) acc[i][jp] = 0ull;

    const int ty = tid >> 4;     // 0..15
    const int tx = tid & 15;     // 0..15

    // prologue: stage tile 0 into buffer 0
    float4 av = *(const float4*)(Ap);
    float4 wv = *(const float4*)(Wp);
    *(ull*)&As2[0][kq + 0][2 * r] = dup2(av.x);
    *(ull*)&As2[0][kq + 1][2 * r] = dup2(av.y);
    *(ull*)&As2[0][kq + 2][2 * r] = dup2(av.z);
    *(ull*)&As2[0][kq + 3][2 * r] = dup2(av.w);
    Bs[0][kq + 0][r] = wv.x; Bs[0][kq + 1][r] = wv.y;
    Bs[0][kq + 2][r] = wv.z; Bs[0][kq + 3][r] = wv.w;
    __syncthreads();

    for (int it = 1; it <= 32; it++) {
        const int cur = (it - 1) & 1;
        const int nxt = it & 1;
        if (it < 32) {
            av = *(const float4*)(Ap + it * 8);
            wv = *(const float4*)(Wp + it * 8);
        }
#pragma unroll
        for (int kk = 0; kk < 8; kk++) {
            const ulonglong2 b01 = *(const ulonglong2*)&Bs[cur][kk][tx * 8];
            const ulonglong2 b23 = *(const ulonglong2*)&Bs[cur][kk][tx * 8 + 4];
#pragma unroll
            for (int ip = 0; ip < 4; ip++) {
                const ulonglong2 ad = *(const ulonglong2*)&As2[cur][kk][2 * (ty * 8 + 2 * ip)];
                fma2(acc[2 * ip    ][0], ad.x, b01.x);
                fma2(acc[2 * ip    ][1], ad.x, b01.y);
                fma2(acc[2 * ip    ][2], ad.x, b23.x);
                fma2(acc[2 * ip    ][3], ad.x, b23.y);
                fma2(acc[2 * ip + 1][0], ad.y, b01.x);
                fma2(acc[2 * ip + 1][1], ad.y, b01.y);
                fma2(acc[2 * ip + 1][2], ad.y, b23.x);
                fma2(acc[2 * ip + 1][3], ad.y, b23.y);
            }
        }
        if (it < 32) {
            *(ull*)&As2[nxt][kq + 0][2 * r] = dup2(av.x);
            *(ull*)&As2[nxt][kq + 1][2 * r] = dup2(av.y);
            *(ull*)&As2[nxt][kq + 2][2 * r] = dup2(av.z);
            *(ull*)&As2[nxt][kq + 3][2 * r] = dup2(av.w);
            Bs[nxt][kq + 0][r] = wv.x; Bs[nxt][kq + 1][r] = wv.y;
            Bs[nxt][kq + 2][r] = wv.z; Bs[nxt][kq + 3][r] = wv.w;
            __syncthreads();
        }
    }

    if (MODE == M_SCORES) {
        const long R = (long)gridDim.x * 128;
#pragma unroll
        for (int i = 0; i < 8; i++) {
            float p = 0.0f;
#pragma unroll
            for (int jp = 0; jp < 4; jp++) {
                const float2 v = unpack2(acc[i][jp]);
                const int col = colBase + tx * 8 + 2 * jp;
                p += tanh_acc(v.x + bias[col])     * e0[col];
                p += tanh_acc(v.y + bias[col + 1]) * e0[col + 1];
            }
            p += __shfl_xor_sync(0xffffffffu, p, 8);
            p += __shfl_xor_sync(0xffffffffu, p, 4);
            p += __shfl_xor_sync(0xffffffffu, p, 2);
            p += __shfl_xor_sync(0xffffffffu, p, 1);
            if (tx == 0)
                eout[(long)blockIdx.y * R + rowBase + ty * 8 + i] = p;
        }
        return;
    }

#pragma unroll
    for (int i = 0; i < 8; i++) {
        const int row = rowBase + ty * 8 + i;
#pragma unroll
        for (int jp = 0; jp < 4; jp++) {
            const float2 vv = unpack2(acc[i][jp]);
#pragma unroll
            for (int h = 0; h < 2; h++) {
                const int col = colBase + tx * 8 + 2 * jp + h;
                const long idx = (long)row * 256 + col;
                const float v = h ? vv.y : vv.x;
                if (MODE == M_TANHB) {
                    outp[idx] = tanh_acc(v + bias[col]);
                } else if (MODE == M_Z) {
                    outp[idx] = sigmoid_acc(v + outp[idx]);
                } else if (MODE == M_R0 || MODE == M_R1) {
                    const int jn = row >> 12, b = row & 4095;
                    const long crow = ((long)(2 * (start + jn) + 1 + kchild) << 12) + b;
                    const float c = A[crow * 256 + col];
                    float val = sigmoid_acc(v + e0[idx]) * c;
                    if (MODE == M_R1) val += outp[idx];
                    outp[idx] = val;
                } else if (MODE == M_FINAL) {
                    const float nv = tanh_acc(v + e0[idx]);
                    const float z  = e1[idx];
                    const float hs = e2[idx];
                    const int jn = row >> 12, b = row & 4095;
                    const float m = e3[(long)(start + jn) * BATCH + b];
                    outp[((long)start * BATCH + row) * 256 + col] = ((1.0f - z) * nv + z * hs) * m;
                } else if (MODE == M_OUT) {
                    outp[(long)row * 128 + col] = v + bias[col];
                }
            }
        }
    }
}

// fused xi kernel: all three K=32 input projections in one pass
__global__ void __launch_bounds__(256)
xi3_kernel(const float* __restrict__ x,
           const float* __restrict__ Wr, const float* __restrict__ br1, const float* __restrict__ br2,
           const float* __restrict__ Wz, const float* __restrict__ bz1, const float* __restrict__ bz2,
           const float* __restrict__ Wn, const float* __restrict__ bn1, const float* __restrict__ bn2,
           float* __restrict__ outr, float* __restrict__ outz, float* __restrict__ outn)
{
    const int o = threadIdx.x;
    float wr[32], wz[32], wn[32];
#pragma unroll
    for (int i = 0; i < 32; i++) {
        wr[i] = Wr[o * 32 + i];
        wz[i] = Wz[o * 32 + i];
        wn[i] = Wn[o * 32 + i];
    }
    const float biasr = br1[o] + br2[o];
    const float biasz = bz1[o] + bz2[o];
    const float biasn = bn1[o] + bn2[o];

    __shared__ float xs[32][33];
    const long rowBase = (long)blockIdx.x * 32;
    {
        const int rr = threadIdx.x >> 3;
        const int cc = (threadIdx.x & 7) * 4;
        const float4 v = *(const float4*)(x + (rowBase + rr) * 32 + cc);
        xs[rr][cc] = v.x; xs[rr][cc + 1] = v.y; xs[rr][cc + 2] = v.z; xs[rr][cc + 3] = v.w;
    }
    __syncthreads();
    for (int rr = 0; rr < 32; rr++) {
        float sr = biasr, sz = biasz, sn = biasn;
#pragma unroll
        for (int i = 0; i < 32; i++) {
            const float xv = xs[rr][i];
            sr = fmaf(xv, wr[i], sr);
            sz = fmaf(xv, wz[i], sz);
            sn = fmaf(xv, wn[i], sn);
        }
        const long idx = (rowBase + rr) * 256 + o;
        outr[idx] = sr;
        outz[idx] = sz;
        outn[idx] = sn;
    }
}

// Leaf level: h = (1 - sigmoid(x.wiz + bz)) * tanh(x.win + bn) * mask
__global__ void __launch_bounds__(256)
leaf_kernel(const float* __restrict__ x,
            const float* __restrict__ wiz, const float* __restrict__ wiz_b, const float* __restrict__ whz_b,
            const float* __restrict__ win, const float* __restrict__ win_b, const float* __restrict__ whn_b,
            const float* __restrict__ maskp, float* __restrict__ outp)
{
    const int o = threadIdx.x;
    float wz[32], wn[32];
#pragma unroll
    for (int i = 0; i < 32; i++) { wz[i] = wiz[o * 32 + i]; wn[i] = win[o * 32 + i]; }
    const float bz = wiz_b[o] + whz_b[o];
    const float bn = win_b[o] + whn_b[o];

    __shared__ float xs[32][33];
    __shared__ float ms[32];
    const long rowBase = (long)blockIdx.x * 32;
    {
        const int rr = threadIdx.x >> 3;
        const int cc = (threadIdx.x & 7) * 4;
        const float4 v = *(const float4*)(x + (rowBase + rr) * 32 + cc);
        xs[rr][cc] = v.x; xs[rr][cc + 1] = v.y; xs[rr][cc + 2] = v.z; xs[rr][cc + 3] = v.w;
    }
    if (threadIdx.x < 32) ms[threadIdx.x] = maskp[rowBase + threadIdx.x];
    __syncthreads();
    for (int rr = 0; rr < 32; rr++) {
        float sz = bz, sn = bn;
#pragma unroll
        for (int i = 0; i < 32; i++) {
            sz = fmaf(xs[rr][i], wz[i], sz);
            sn = fmaf(xs[rr][i], wn[i], sn);
        }
        const float zg = sigmoid_acc(sz);
        outp[(rowBase + rr) * 256 + o] = (1.0f - zg) * tanh_acc(sn) * ms[rr];
    }
}

// combine score partials: scores[k*R+row] = w_b + part[k][0][row] + part[k][1][row]
__global__ void combine_scores(const float* __restrict__ part, float* __restrict__ scores,
                               const float* __restrict__ wb, int R)
{
    const int i = blockIdx.x * 256 + threadIdx.x;
    if (i < 2 * R) {
        const int k = i / R, row = i - k * R;
        scores[i] = wb[0] + (part[(long)k * 2 * R + row] + part[(long)k * 2 * R + R + row]);
    }
}

// g = a0*c0 + a1*c1, a_k = scores_k / (scores_0 + scores_1). blockDim=64, grid=R
__global__ void __launch_bounds__(64)
g_kernel(const float* __restrict__ Hall, const float* __restrict__ scores,
         float* __restrict__ gp, int R, int start)
{
    const int row = blockIdx.x;
    const int jn = row >> 12, b = row & 4095;
    const long c0row = ((long)(2 * (start + jn) + 1) << 12) + b;
    const float s0 = scores[row], s1 = scores[R + row];
    const float inv = 1.0f / (s0 + s1);
    const float a0 = s0 * inv, a1 = s1 * inv;
    const int c = threadIdx.x * 4;
    const float4 c0 = *(const float4*)(Hall + c0row * 256 + c);
    const float4 c1 = *(const float4*)(Hall + (c0row + 4096) * 256 + c);
    float4 g;
    g.x = a0 * c0.x + a1 * c1.x;
    g.y = a0 * c0.y + a1 * c1.y;
    g.z = a0 * c0.z + a1 * c1.z;
    g.w = a0 * c0.w + a1 * c1.w;
    *(float4*)(gp + (long)row * 256 + c) = g;
}

extern "C" void kernel_launch(void* const* d_in, const int* in_sizes, int n_in,
                              void* d_out, int out_size)
{
    const float* targets = (const float*)d_in[0];
    const float* mask    = (const float*)d_in[1];
    const float* wir_w = (const float*)d_in[2];  const float* wir_b = (const float*)d_in[3];
    const float* whr_w = (const float*)d_in[4];  const float* whr_b = (const float*)d_in[5];
    const float* wiz_w = (const float*)d_in[6];  const float* wiz_b = (const float*)d_in[7];
    const float* whz_w = (const float*)d_in[8];  const float* whz_b = (const float*)d_in[9];
    const float* win_w = (const float*)d_in[10]; const float* win_b = (const float*)d_in[11];
    const float* whn_w = (const float*)d_in[12]; const float* whn_b = (const float*)d_in[13];
    const float* wms_w = (const float*)d_in[14]; const float* wms_b = (const float*)d_in[15];
    const float* w_w   = (const float*)d_in[16]; const float* w_b   = (const float*)d_in[17];
    const float* wa_w  = (const float*)d_in[18]; const float* wa_b  = (const float*)d_in[19];
    const float* mu_w  = (const float*)d_in[20]; const float* mu_b  = (const float*)d_in[21];
    const float* lv_w  = (const float*)d_in[22]; const float* lv_b  = (const float*)d_in[23];
    float* outp = (float*)d_out;

    float *Hall, *g, *cs, *xir, *xiz, *xin, *scores, *spart;
    cudaGetSymbolAddress((void**)&Hall,   d_Hall);
    cudaGetSymbolAddress((void**)&g,      d_g);
    cudaGetSymbolAddress((void**)&cs,     d_cs);
    cudaGetSymbolAddress((void**)&xir,    d_xir);
    cudaGetSymbolAddress((void**)&xiz,    d_xiz);
    cudaGetSymbolAddress((void**)&xin,    d_xin);
    cudaGetSymbolAddress((void**)&scores, d_scores);
    cudaGetSymbolAddress((void**)&spart,  d_spart);

    // ---- Leaf level: d = 6, start = 63, n = 64 ----
    {
        const long start = 63;
        leaf_kernel<<<(64 * BATCH) / 32, 256>>>(
            targets + start * BATCH * IDIM,
            wiz_w, wiz_b, whz_b, win_w, win_b, whn_b,
            mask + start * BATCH,
            Hall + start * BATCH * HDIM);
    }

    // ---- Internal levels d = 5 .. 0 ----
    for (int d = 5; d >= 0; d--) {
        const int start = (1 << d) - 1;
        const int n = 1 << d;
        const int R = n * BATCH;
        const float* x = targets + (long)start * BATCH * IDIM;
        dim3 gg(R / 128, 2);

        // scores_k = w_b + sum_g tanh(c_k @ wms[k]^T + wms_b[k]) * w_w
        gemm256<M_SCORES><<<gg, 256>>>(Hall, wms_w,         wms_b,       nullptr, w_w, nullptr, nullptr, nullptr, spart,               start, 0);
        gemm256<M_SCORES><<<gg, 256>>>(Hall, wms_w + 65536, wms_b + 256, nullptr, w_w, nullptr, nullptr, nullptr, spart + (long)2 * R, start, 1);
        combine_scores<<<(2 * R + 255) / 256, 256>>>(spart, scores, w_b, R);

        // g = a0*c0 + a1*c1
        g_kernel<<<R, 64>>>(Hall, scores, g, R, start);

        // child_sum = tanh(g @ wa^T + wa_b)
        gemm256<M_TANHB><<<gg, 256>>>(g, wa_w, wa_b, cs, nullptr, nullptr, nullptr, nullptr, nullptr, start, 0);

        // xi precomputations (bias pairs folded), fused
        xi3_kernel<<<R / 32, 256>>>(x,
                                    wir_w, wir_b, whr_b,
                                    wiz_w, wiz_b, whz_b,
                                    win_w, win_b, whn_b,
                                    xir, xiz, xin);

        // z = sigmoid(xiz + child_sum @ whz^T)
        gemm256<M_Z><<<gg, 256>>>(cs, whz_w, nullptr, xiz, nullptr, nullptr, nullptr, nullptr, nullptr, start, 0);

        // s = sum_k sigmoid(xir + c_k @ whr^T) * c_k   (into g buffer)
        gemm256<M_R0><<<gg, 256>>>(Hall, whr_w, nullptr, g, xir, nullptr, nullptr, nullptr, nullptr, start, 0);
        gemm256<M_R1><<<gg, 256>>>(Hall, whr_w, nullptr, g, xir, nullptr, nullptr, nullptr, nullptr, start, 1);

        // n = tanh(xin + s @ whn^T); h = ((1-z)*n + z*cs) * mask -> Hall
        gemm256<M_FINAL><<<gg, 256>>>(g, whn_w, nullptr, Hall, xin, xiz, cs, mask, nullptr, start, 0);
    }

    // ---- Output heads ----
    dim3 go(BATCH / 128, 1);
    gemm256<M_OUT><<<go, 256>>>(Hall, mu_w, mu_b, outp,                     nullptr, nullptr, nullptr, nullptr, nullptr, 0, 0);
    gemm256<M_OUT><<<go, 256>>>(Hall, lv_w, lv_b, outp + (long)BATCH * 128, nullptr, nullptr, nullptr, nullptr, nullptr, 0, 0);
}

// round 9
// speedup vs baseline: 1.1002x; 1.1002x over previous
#include <cuda_runtime.h>
#include <math.h>

// Problem constants
#define BATCH 4096
#define HDIM  256
#define IDIM  32
#define NNODES 127
#define MAXR  (32 * BATCH)   // largest internal-level row count (d=5)

// ---------------- static device scratch (allowed workaround) ----------------
__device__ float d_Hall[(size_t)NNODES * BATCH * HDIM];  // all node hiddens
__device__ float d_g  [(size_t)MAXR * HDIM];             // g, then s
__device__ float d_cs [(size_t)MAXR * HDIM];             // child_sum
__device__ float d_xir[(size_t)MAXR * HDIM];             // x@wir + wir_b + whr_b
__device__ float d_xiz[(size_t)MAXR * HDIM];             // x@wiz + biases, then z
__device__ float d_xin[(size_t)MAXR * HDIM];             // x@win + biases
__device__ float d_scores[2 * MAXR];
__device__ float d_spart[4 * MAXR];                      // score partials [k][y][row]

// ---------------- accurate activations (immune to --use_fast_math) ----------
__device__ __forceinline__ float tanh_acc(float x) {
    const float ax = fabsf(x);
    if (ax < 0.25f) {
        const float x2 = x * x;
        float p = fmaf(x2, 0.021869488f, -0.053968254f);
        p = fmaf(x2, p, 0.13333334f);
        p = fmaf(x2, p, -0.33333334f);
        return fmaf(x2 * x, p, x);
    }
    const float t = __expf(2.0f * ax);
    const float r = 1.0f - 2.0f / (t + 1.0f);
    return copysignf(r, x);
}

__device__ __forceinline__ float sigmoid_acc(float x) {
    const float e = __expf(-fabsf(x));
    const float s = 1.0f / (1.0f + e);
    return x >= 0.0f ? s : e * s;
}

// packed f32x2 helpers (FFMA2 — 2 IEEE fp32 FMAs per instruction)
typedef unsigned long long ull;
__device__ __forceinline__ ull dup2(float a) {
    ull r;
    asm("mov.b64 %0, {%1, %1};" : "=l"(r) : "f"(a));
    return r;
}
__device__ __forceinline__ void fma2(ull& d, ull a, ull b) {
    asm("fma.rn.f32x2 %0, %1, %2, %0;" : "+l"(d) : "l"(a), "l"(b));
}
__device__ __forceinline__ float2 unpack2(ull v) {
    float lo, hi;
    asm("mov.b64 {%0, %1}, %2;" : "=f"(lo), "=f"(hi) : "l"(v));
    return make_float2(lo, hi);
}

// ---------------- GEMM modes ----------------
#define M_SCORES 0
#define M_TANHB  1
#define M_Z      2
#define M_R0     3
#define M_R1     4
#define M_FINAL  5
#define M_OUT    6

// Generic K=256 SGEMM (exact fp32, FFMA2 inner loop), tile 128x128x16,
// 256 threads, 8x8/thread. R7 staging pattern (conflict-free), BK=16:
// half the barriers, MLP-4 global loads, register prefetch.
template<int MODE>
__global__ void __launch_bounds__(256)
gemm256(const float* __restrict__ A,
        const float* __restrict__ W,    // N x 256 row-major
        const float* __restrict__ bias,
        float* __restrict__ outp,
        const float* __restrict__ e0,
        const float* __restrict__ e1,
        const float* __restrict__ e2,
        const float* __restrict__ e3,
        float* __restrict__ eout,
        int start, int kchild)
{
    __shared__ __align__(16) float As[16][132];
    __shared__ __align__(16) float Bs[16][132];

    const int tid = threadIdx.x;
    const int rowBase = blockIdx.x * 128;
    const int colBase = blockIdx.y * 128;

    const int r  = tid >> 1;
    const int kq = (tid & 1) * 4;
    const int row_g = rowBase + r;

    long arow;
    if (MODE == M_SCORES || MODE == M_R0 || MODE == M_R1) {
        const int jn = row_g >> 12;
        const int b  = row_g & 4095;
        arow = ((long)(2 * (start + jn) + 1 + kchild) << 12) + b;
    } else {
        arow = row_g;
    }
    const float* Ap = A + arow * 256 + kq;
    const float* Wp = W + (long)(colBase + r) * 256 + kq;

    ull acc[8][4];
#pragma unroll
    for (int i = 0; i < 8; i++)
#pragma unroll
        for (int jp = 0; jp < 4; jp++) acc[i][jp] = 0ull;

    const int ty = tid >> 4;     // 0..15
    const int tx = tid & 15;     // 0..15

    // prefetch tile 0 (two 8-float chunks each for A and W)
    float4 av0 = *(const float4*)(Ap);
    float4 av1 = *(const float4*)(Ap + 8);
    float4 wv0 = *(const float4*)(Wp);
    float4 wv1 = *(const float4*)(Wp + 8);

    for (int it = 0; it < 16; it++) {
        __syncthreads();
        // chunk 0: rows kq..kq+3 ; chunk 1: rows kq+8..kq+11  (R7-style, conflict-free)
        As[kq + 0][r] = av0.x; As[kq + 1][r] = av0.y; As[kq + 2][r] = av0.z; As[kq + 3][r] = av0.w;
        As[kq + 8][r] = av1.x; As[kq + 9][r] = av1.y; As[kq + 10][r] = av1.z; As[kq + 11][r] = av1.w;
        Bs[kq + 0][r] = wv0.x; Bs[kq + 1][r] = wv0.y; Bs[kq + 2][r] = wv0.z; Bs[kq + 3][r] = wv0.w;
        Bs[kq + 8][r] = wv1.x; Bs[kq + 9][r] = wv1.y; Bs[kq + 10][r] = wv1.z; Bs[kq + 11][r] = wv1.w;
        __syncthreads();
        if (it < 15) {
            av0 = *(const float4*)(Ap + (it + 1) * 16);
            av1 = *(const float4*)(Ap + (it + 1) * 16 + 8);
            wv0 = *(const float4*)(Wp + (it + 1) * 16);
            wv1 = *(const float4*)(Wp + (it + 1) * 16 + 8);
        }
#pragma unroll
        for (int kk = 0; kk < 16; kk++) {
            const ull* Bp = (const ull*)&Bs[kk][tx * 8];
            ull bp[4];
#pragma unroll
            for (int jp = 0; jp < 4; jp++) bp[jp] = Bp[jp];
#pragma unroll
            for (int i = 0; i < 8; i++) {
                const ull ad = dup2(As[kk][ty * 8 + i]);
#pragma unroll
                for (int jp = 0; jp < 4; jp++)
                    fma2(acc[i][jp], ad, bp[jp]);
            }
        }
    }

    if (MODE == M_SCORES) {
        const long R = (long)gridDim.x * 128;
#pragma unroll
        for (int i = 0; i < 8; i++) {
            float p = 0.0f;
#pragma unroll
            for (int jp = 0; jp < 4; jp++) {
                const float2 v = unpack2(acc[i][jp]);
                const int col = colBase + tx * 8 + 2 * jp;
                p += tanh_acc(v.x + bias[col])     * e0[col];
                p += tanh_acc(v.y + bias[col + 1]) * e0[col + 1];
            }
            p += __shfl_xor_sync(0xffffffffu, p, 8);
            p += __shfl_xor_sync(0xffffffffu, p, 4);
            p += __shfl_xor_sync(0xffffffffu, p, 2);
            p += __shfl_xor_sync(0xffffffffu, p, 1);
            if (tx == 0)
                eout[(long)blockIdx.y * R + rowBase + ty * 8 + i] = p;
        }
        return;
    }

#pragma unroll
    for (int i = 0; i < 8; i++) {
        const int row = rowBase + ty * 8 + i;
#pragma unroll
        for (int jp = 0; jp < 4; jp++) {
            const float2 vv = unpack2(acc[i][jp]);
#pragma unroll
            for (int h = 0; h < 2; h++) {
                const int col = colBase + tx * 8 + 2 * jp + h;
                const long idx = (long)row * 256 + col;
                const float v = h ? vv.y : vv.x;
                if (MODE == M_TANHB) {
                    outp[idx] = tanh_acc(v + bias[col]);
                } else if (MODE == M_Z) {
                    outp[idx] = sigmoid_acc(v + outp[idx]);
                } else if (MODE == M_R0 || MODE == M_R1) {
                    const int jn = row >> 12, b = row & 4095;
                    const long crow = ((long)(2 * (start + jn) + 1 + kchild) << 12) + b;
                    const float c = A[crow * 256 + col];
                    float val = sigmoid_acc(v + e0[idx]) * c;
                    if (MODE == M_R1) val += outp[idx];
                    outp[idx] = val;
                } else if (MODE == M_FINAL) {
                    const float nv = tanh_acc(v + e0[idx]);
                    const float z  = e1[idx];
                    const float hs = e2[idx];
                    const int jn = row >> 12, b = row & 4095;
                    const float m = e3[(long)(start + jn) * BATCH + b];
                    outp[((long)start * BATCH + row) * 256 + col] = ((1.0f - z) * nv + z * hs) * m;
                } else if (MODE == M_OUT) {
                    outp[(long)row * 128 + col] = v + bias[col];
                }
            }
        }
    }
}

// fused xi kernel: all three K=32 input projections in one pass
__global__ void __launch_bounds__(256)
xi3_kernel(const float* __restrict__ x,
           const float* __restrict__ Wr, const float* __restrict__ br1, const float* __restrict__ br2,
           const float* __restrict__ Wz, const float* __restrict__ bz1, const float* __restrict__ bz2,
           const float* __restrict__ Wn, const float* __restrict__ bn1, const float* __restrict__ bn2,
           float* __restrict__ outr, float* __restrict__ outz, float* __restrict__ outn)
{
    const int o = threadIdx.x;
    float wr[32], wz[32], wn[32];
#pragma unroll
    for (int i = 0; i < 32; i++) {
        wr[i] = Wr[o * 32 + i];
        wz[i] = Wz[o * 32 + i];
        wn[i] = Wn[o * 32 + i];
    }
    const float biasr = br1[o] + br2[o];
    const float biasz = bz1[o] + bz2[o];
    const float biasn = bn1[o] + bn2[o];

    __shared__ float xs[32][33];
    const long rowBase = (long)blockIdx.x * 32;
    {
        const int rr = threadIdx.x >> 3;
        const int cc = (threadIdx.x & 7) * 4;
        const float4 v = *(const float4*)(x + (rowBase + rr) * 32 + cc);
        xs[rr][cc] = v.x; xs[rr][cc + 1] = v.y; xs[rr][cc + 2] = v.z; xs[rr][cc + 3] = v.w;
    }
    __syncthreads();
    for (int rr = 0; rr < 32; rr++) {
        float sr = biasr, sz = biasz, sn = biasn;
#pragma unroll
        for (int i = 0; i < 32; i++) {
            const float xv = xs[rr][i];
            sr = fmaf(xv, wr[i], sr);
            sz = fmaf(xv, wz[i], sz);
            sn = fmaf(xv, wn[i], sn);
        }
        const long idx = (rowBase + rr) * 256 + o;
        outr[idx] = sr;
        outz[idx] = sz;
        outn[idx] = sn;
    }
}

// Leaf level: h = (1 - sigmoid(x.wiz + bz)) * tanh(x.win + bn) * mask
__global__ void __launch_bounds__(256)
leaf_kernel(const float* __restrict__ x,
            const float* __restrict__ wiz, const float* __restrict__ wiz_b, const float* __restrict__ whz_b,
            const float* __restrict__ win, const float* __restrict__ win_b, const float* __restrict__ whn_b,
            const float* __restrict__ maskp, float* __restrict__ outp)
{
    const int o = threadIdx.x;
    float wz[32], wn[32];
#pragma unroll
    for (int i = 0; i < 32; i++) { wz[i] = wiz[o * 32 + i]; wn[i] = win[o * 32 + i]; }
    const float bz = wiz_b[o] + whz_b[o];
    const float bn = win_b[o] + whn_b[o];

    __shared__ float xs[32][33];
    __shared__ float ms[32];
    const long rowBase = (long)blockIdx.x * 32;
    {
        const int rr = threadIdx.x >> 3;
        const int cc = (threadIdx.x & 7) * 4;
        const float4 v = *(const float4*)(x + (rowBase + rr) * 32 + cc);
        xs[rr][cc] = v.x; xs[rr][cc + 1] = v.y; xs[rr][cc + 2] = v.z; xs[rr][cc + 3] = v.w;
    }
    if (threadIdx.x < 32) ms[threadIdx.x] = maskp[rowBase + threadIdx.x];
    __syncthreads();
    for (int rr = 0; rr < 32; rr++) {
        float sz = bz, sn = bn;
#pragma unroll
        for (int i = 0; i < 32; i++) {
            sz = fmaf(xs[rr][i], wz[i], sz);
            sn = fmaf(xs[rr][i], wn[i], sn);
        }
        const float zg = sigmoid_acc(sz);
        outp[(rowBase + rr) * 256 + o] = (1.0f - zg) * tanh_acc(sn) * ms[rr];
    }
}

// combine score partials: scores[k*R+row] = w_b + part[k][0][row] + part[k][1][row]
__global__ void combine_scores(const float* __restrict__ part, float* __restrict__ scores,
                               const float* __restrict__ wb, int R)
{
    const int i = blockIdx.x * 256 + threadIdx.x;
    if (i < 2 * R) {
        const int k = i / R, row = i - k * R;
        scores[i] = wb[0] + (part[(long)k * 2 * R + row] + part[(long)k * 2 * R + R + row]);
    }
}

// g = a0*c0 + a1*c1, a_k = scores_k / (scores_0 + scores_1). blockDim=64, grid=R
__global__ void __launch_bounds__(64)
g_kernel(const float* __restrict__ Hall, const float* __restrict__ scores,
         float* __restrict__ gp, int R, int start)
{
    const int row = blockIdx.x;
    const int jn = row >> 12, b = row & 4095;
    const long c0row = ((long)(2 * (start + jn) + 1) << 12) + b;
    const float s0 = scores[row], s1 = scores[R + row];
    const float inv = 1.0f / (s0 + s1);
    const float a0 = s0 * inv, a1 = s1 * inv;
    const int c = threadIdx.x * 4;
    const float4 c0 = *(const float4*)(Hall + c0row * 256 + c);
    const float4 c1 = *(const float4*)(Hall + (c0row + 4096) * 256 + c);
    float4 g;
    g.x = a0 * c0.x + a1 * c1.x;
    g.y = a0 * c0.y + a1 * c1.y;
    g.z = a0 * c0.z + a1 * c1.z;
    g.w = a0 * c0.w + a1 * c1.w;
    *(float4*)(gp + (long)row * 256 + c) = g;
}

extern "C" void kernel_launch(void* const* d_in, const int* in_sizes, int n_in,
                              void* d_out, int out_size)
{
    const float* targets = (const float*)d_in[0];
    const float* mask    = (const float*)d_in[1];
    const float* wir_w = (const float*)d_in[2];  const float* wir_b = (const float*)d_in[3];
    const float* whr_w = (const float*)d_in[4];  const float* whr_b = (const float*)d_in[5];
    const float* wiz_w = (const float*)d_in[6];  const float* wiz_b = (const float*)d_in[7];
    const float* whz_w = (const float*)d_in[8];  const float* whz_b = (const float*)d_in[9];
    const float* win_w = (const float*)d_in[10]; const float* win_b = (const float*)d_in[11];
    const float* whn_w = (const float*)d_in[12]; const float* whn_b = (const float*)d_in[13];
    const float* wms_w = (const float*)d_in[14]; const float* wms_b = (const float*)d_in[15];
    const float* w_w   = (const float*)d_in[16]; const float* w_b   = (const float*)d_in[17];
    const float* wa_w  = (const float*)d_in[18]; const float* wa_b  = (const float*)d_in[19];
    const float* mu_w  = (const float*)d_in[20]; const float* mu_b  = (const float*)d_in[21];
    const float* lv_w  = (const float*)d_in[22]; const float* lv_b  = (const float*)d_in[23];
    float* outp = (float*)d_out;

    float *Hall, *g, *cs, *xir, *xiz, *xin, *scores, *spart;
    cudaGetSymbolAddress((void**)&Hall,   d_Hall);
    cudaGetSymbolAddress((void**)&g,      d_g);
    cudaGetSymbolAddress((void**)&cs,     d_cs);
    cudaGetSymbolAddress((void**)&xir,    d_xir);
    cudaGetSymbolAddress((void**)&xiz,    d_xiz);
    cudaGetSymbolAddress((void**)&xin,    d_xin);
    cudaGetSymbolAddress((void**)&scores, d_scores);
    cudaGetSymbolAddress((void**)&spart,  d_spart);

    // ---- Leaf level: d = 6, start = 63, n = 64 ----
    {
        const long start = 63;
        leaf_kernel<<<(64 * BATCH) / 32, 256>>>(
            targets + start * BATCH * IDIM,
            wiz_w, wiz_b, whz_b, win_w, win_b, whn_b,
            mask + start * BATCH,
            Hall + start * BATCH * HDIM);
    }

    // ---- Internal levels d = 5 .. 0 ----
    for (int d = 5; d >= 0; d--) {
        const int start = (1 << d) - 1;
        const int n = 1 << d;
        const int R = n * BATCH;
        const float* x = targets + (long)start * BATCH * IDIM;
        dim3 gg(R / 128, 2);

        // scores_k = w_b + sum_g tanh(c_k @ wms[k]^T + wms_b[k]) * w_w
        gemm256<M_SCORES><<<gg, 256>>>(Hall, wms_w,         wms_b,       nullptr, w_w, nullptr, nullptr, nullptr, spart,               start, 0);
        gemm256<M_SCORES><<<gg, 256>>>(Hall, wms_w + 65536, wms_b + 256, nullptr, w_w, nullptr, nullptr, nullptr, spart + (long)2 * R, start, 1);
        combine_scores<<<(2 * R + 255) / 256, 256>>>(spart, scores, w_b, R);

        // g = a0*c0 + a1*c1
        g_kernel<<<R, 64>>>(Hall, scores, g, R, start);

        // child_sum = tanh(g @ wa^T + wa_b)
        gemm256<M_TANHB><<<gg, 256>>>(g, wa_w, wa_b, cs, nullptr, nullptr, nullptr, nullptr, nullptr, start, 0);

        // xi precomputations (bias pairs folded), fused
        xi3_kernel<<<R / 32, 256>>>(x,
                                    wir_w, wir_b, whr_b,
                                    wiz_w, wiz_b, whz_b,
                                    win_w, win_b, whn_b,
                                    xir, xiz, xin);

        // z = sigmoid(xiz + child_sum @ whz^T)
        gemm256<M_Z><<<gg, 256>>>(cs, whz_w, nullptr, xiz, nullptr, nullptr, nullptr, nullptr, nullptr, start, 0);

        // s = sum_k sigmoid(xir + c_k @ whr^T) * c_k   (into g buffer)
        gemm256<M_R0><<<gg, 256>>>(Hall, whr_w, nullptr, g, xir, nullptr, nullptr, nullptr, nullptr, start, 0);
        gemm256<M_R1><<<gg, 256>>>(Hall, whr_w, nullptr, g, xir, nullptr, nullptr, nullptr, nullptr, start, 1);

        // n = tanh(xin + s @ whn^T); h = ((1-z)*n + z*cs) * mask -> Hall
        gemm256<M_FINAL><<<gg, 256>>>(g, whn_w, nullptr, Hall, xin, xiz, cs, mask, nullptr, start, 0);
    }

    // ---- Output heads ----
    dim3 go(BATCH / 128, 1);
    gemm256<M_OUT><<<go, 256>>>(Hall, mu_w, mu_b, outp,                     nullptr, nullptr, nullptr, nullptr, nullptr, 0, 0);
    gemm256<M_OUT><<<go, 256>>>(Hall, lv_w, lv_b, outp + (long)BATCH * 128, nullptr, nullptr, nullptr, nullptr, nullptr, 0, 0);
}

// round 10
// speedup vs baseline: 1.1184x; 1.0166x over previous
#include <cuda_runtime.h>
#include <math.h>

// Problem constants
#define BATCH 4096
#define HDIM  256
#define IDIM  32
#define NNODES 127
#define MAXR  (32 * BATCH)   // largest internal-level row count (d=5)

// ---------------- static device scratch (allowed workaround) ----------------
__device__ float d_Hall[(size_t)NNODES * BATCH * HDIM];  // all node hiddens
__device__ float d_g  [(size_t)MAXR * HDIM];             // g, then s
__device__ float d_cs [(size_t)MAXR * HDIM];             // child_sum
__device__ float d_xir[(size_t)MAXR * HDIM];             // x@wir + wir_b + whr_b
__device__ float d_xiz[(size_t)MAXR * HDIM];             // x@wiz + biases, then z
__device__ float d_xin[(size_t)MAXR * HDIM];             // x@win + biases
__device__ float d_scores[2 * MAXR];
__device__ float d_spart[4 * MAXR];                      // score partials [k][y][row]

// ---------------- accurate activations (immune to --use_fast_math) ----------
__device__ __forceinline__ float tanh_acc(float x) {
    const float ax = fabsf(x);
    if (ax < 0.25f) {
        const float x2 = x * x;
        float p = fmaf(x2, 0.021869488f, -0.053968254f);
        p = fmaf(x2, p, 0.13333334f);
        p = fmaf(x2, p, -0.33333334f);
        return fmaf(x2 * x, p, x);
    }
    const float t = __expf(2.0f * ax);
    const float r = 1.0f - 2.0f / (t + 1.0f);
    return copysignf(r, x);
}

__device__ __forceinline__ float sigmoid_acc(float x) {
    const float e = __expf(-fabsf(x));
    const float s = 1.0f / (1.0f + e);
    return x >= 0.0f ? s : e * s;
}

// packed f32x2 helpers (FFMA2 — 2 IEEE fp32 FMAs per instruction)
typedef unsigned long long ull;
__device__ __forceinline__ ull dup2(float a) {
    ull r;
    asm("mov.b64 %0, {%1, %1};" : "=l"(r) : "f"(a));
    return r;
}
__device__ __forceinline__ void fma2(ull& d, ull a, ull b) {
    asm("fma.rn.f32x2 %0, %1, %2, %0;" : "+l"(d) : "l"(a), "l"(b));
}
__device__ __forceinline__ float2 unpack2(ull v) {
    float lo, hi;
    asm("mov.b64 {%0, %1}, %2;" : "=f"(lo), "=f"(hi) : "l"(v));
    return make_float2(lo, hi);
}

// ---------------- GEMM modes ----------------
#define M_SCORES 0
#define M_TANHB  1
#define M_Z      2
#define M_R0     3
#define M_R1     4
#define M_FINAL  5
#define M_OUT    6

// Generic K=256 SGEMM (exact fp32, FFMA2 inner loop), tile 128x128x16,
// 256 threads, 8x8/thread. R9 core + 2 blocks/SM + LDS.128 B-fragment reads.
template<int MODE>
__global__ void __launch_bounds__(256, 2)
gemm256(const float* __restrict__ A,
        const float* __restrict__ W,    // N x 256 row-major
        const float* __restrict__ bias,
        float* __restrict__ outp,
        const float* __restrict__ e0,
        const float* __restrict__ e1,
        const float* __restrict__ e2,
        const float* __restrict__ e3,
        float* __restrict__ eout,
        int start, int kchild)
{
    __shared__ __align__(16) float As[16][132];
    __shared__ __align__(16) float Bs[16][132];

    const int tid = threadIdx.x;
    const int rowBase = blockIdx.x * 128;
    const int colBase = blockIdx.y * 128;

    const int r  = tid >> 1;
    const int kq = (tid & 1) * 4;
    const int row_g = rowBase + r;

    long arow;
    if (MODE == M_SCORES || MODE == M_R0 || MODE == M_R1) {
        const int jn = row_g >> 12;
        const int b  = row_g & 4095;
        arow = ((long)(2 * (start + jn) + 1 + kchild) << 12) + b;
    } else {
        arow = row_g;
    }
    const float* Ap = A + arow * 256 + kq;
    const float* Wp = W + (long)(colBase + r) * 256 + kq;

    ull acc[8][4];
#pragma unroll
    for (int i = 0; i < 8; i++)
#pragma unroll
        for (int jp = 0; jp < 4; jp++) acc[i][jp] = 0ull;

    const int ty = tid >> 4;     // 0..15
    const int tx = tid & 15;     // 0..15

    // prefetch tile 0 (two 8-float chunks each for A and W)
    float4 av0 = *(const float4*)(Ap);
    float4 av1 = *(const float4*)(Ap + 8);
    float4 wv0 = *(const float4*)(Wp);
    float4 wv1 = *(const float4*)(Wp + 8);

    for (int it = 0; it < 16; it++) {
        __syncthreads();
        // chunk 0: rows kq..kq+3 ; chunk 1: rows kq+8..kq+11  (conflict-free)
        As[kq + 0][r] = av0.x; As[kq + 1][r] = av0.y; As[kq + 2][r] = av0.z; As[kq + 3][r] = av0.w;
        As[kq + 8][r] = av1.x; As[kq + 9][r] = av1.y; As[kq + 10][r] = av1.z; As[kq + 11][r] = av1.w;
        Bs[kq + 0][r] = wv0.x; Bs[kq + 1][r] = wv0.y; Bs[kq + 2][r] = wv0.z; Bs[kq + 3][r] = wv0.w;
        Bs[kq + 8][r] = wv1.x; Bs[kq + 9][r] = wv1.y; Bs[kq + 10][r] = wv1.z; Bs[kq + 11][r] = wv1.w;
        __syncthreads();
        if (it < 15) {
            av0 = *(const float4*)(Ap + (it + 1) * 16);
            av1 = *(const float4*)(Ap + (it + 1) * 16 + 8);
            wv0 = *(const float4*)(Wp + (it + 1) * 16);
            wv1 = *(const float4*)(Wp + (it + 1) * 16 + 8);
        }
#pragma unroll
        for (int kk = 0; kk < 16; kk++) {
            // B pairs: two 16B shared loads (row stride 132 floats = 528B = 33*16B aligned)
            const ulonglong2 b01 = *(const ulonglong2*)&Bs[kk][tx * 8];
            const ulonglong2 b23 = *(const ulonglong2*)&Bs[kk][tx * 8 + 4];
#pragma unroll
            for (int i = 0; i < 8; i++) {
                const ull ad = dup2(As[kk][ty * 8 + i]);
                fma2(acc[i][0], ad, b01.x);
                fma2(acc[i][1], ad, b01.y);
                fma2(acc[i][2], ad, b23.x);
                fma2(acc[i][3], ad, b23.y);
            }
        }
    }

    if (MODE == M_SCORES) {
        const long R = (long)gridDim.x * 128;
#pragma unroll
        for (int i = 0; i < 8; i++) {
            float p = 0.0f;
#pragma unroll
            for (int jp = 0; jp < 4; jp++) {
                const float2 v = unpack2(acc[i][jp]);
                const int col = colBase + tx * 8 + 2 * jp;
                p += tanh_acc(v.x + bias[col])     * e0[col];
                p += tanh_acc(v.y + bias[col + 1]) * e0[col + 1];
            }
            p += __shfl_xor_sync(0xffffffffu, p, 8);
            p += __shfl_xor_sync(0xffffffffu, p, 4);
            p += __shfl_xor_sync(0xffffffffu, p, 2);
            p += __shfl_xor_sync(0xffffffffu, p, 1);
            if (tx == 0)
                eout[(long)blockIdx.y * R + rowBase + ty * 8 + i] = p;
        }
        return;
    }

#pragma unroll
    for (int i = 0; i < 8; i++) {
        const int row = rowBase + ty * 8 + i;
#pragma unroll
        for (int jp = 0; jp < 4; jp++) {
            const float2 vv = unpack2(acc[i][jp]);
#pragma unroll
            for (int h = 0; h < 2; h++) {
                const int col = colBase + tx * 8 + 2 * jp + h;
                const long idx = (long)row * 256 + col;
                const float v = h ? vv.y : vv.x;
                if (MODE == M_TANHB) {
                    outp[idx] = tanh_acc(v + bias[col]);
                } else if (MODE == M_Z) {
                    outp[idx] = sigmoid_acc(v + outp[idx]);
                } else if (MODE == M_R0 || MODE == M_R1) {
                    const int jn = row >> 12, b = row & 4095;
                    const long crow = ((long)(2 * (start + jn) + 1 + kchild) << 12) + b;
                    const float c = A[crow * 256 + col];
                    float val = sigmoid_acc(v + e0[idx]) * c;
                    if (MODE == M_R1) val += outp[idx];
                    outp[idx] = val;
                } else if (MODE == M_FINAL) {
                    const float nv = tanh_acc(v + e0[idx]);
                    const float z  = e1[idx];
                    const float hs = e2[idx];
                    const int jn = row >> 12, b = row & 4095;
                    const float m = e3[(long)(start + jn) * BATCH + b];
                    outp[((long)start * BATCH + row) * 256 + col] = ((1.0f - z) * nv + z * hs) * m;
                } else if (MODE == M_OUT) {
                    outp[(long)row * 128 + col] = v + bias[col];
                }
            }
        }
    }
}

// fused xi kernel: all three K=32 input projections in one pass
__global__ void __launch_bounds__(256)
xi3_kernel(const float* __restrict__ x,
           const float* __restrict__ Wr, const float* __restrict__ br1, const float* __restrict__ br2,
           const float* __restrict__ Wz, const float* __restrict__ bz1, const float* __restrict__ bz2,
           const float* __restrict__ Wn, const float* __restrict__ bn1, const float* __restrict__ bn2,
           float* __restrict__ outr, float* __restrict__ outz, float* __restrict__ outn)
{
    const int o = threadIdx.x;
    float wr[32], wz[32], wn[32];
#pragma unroll
    for (int i = 0; i < 32; i++) {
        wr[i] = Wr[o * 32 + i];
        wz[i] = Wz[o * 32 + i];
        wn[i] = Wn[o * 32 + i];
    }
    const float biasr = br1[o] + br2[o];
    const float biasz = bz1[o] + bz2[o];
    const float biasn = bn1[o] + bn2[o];

    __shared__ float xs[32][33];
    const long rowBase = (long)blockIdx.x * 32;
    {
        const int rr = threadIdx.x >> 3;
        const int cc = (threadIdx.x & 7) * 4;
        const float4 v = *(const float4*)(x + (rowBase + rr) * 32 + cc);
        xs[rr][cc] = v.x; xs[rr][cc + 1] = v.y; xs[rr][cc + 2] = v.z; xs[rr][cc + 3] = v.w;
    }
    __syncthreads();
    for (int rr = 0; rr < 32; rr++) {
        float sr = biasr, sz = biasz, sn = biasn;
#pragma unroll
        for (int i = 0; i < 32; i++) {
            const float xv = xs[rr][i];
            sr = fmaf(xv, wr[i], sr);
            sz = fmaf(xv, wz[i], sz);
            sn = fmaf(xv, wn[i], sn);
        }
        const long idx = (rowBase + rr) * 256 + o;
        outr[idx] = sr;
        outz[idx] = sz;
        outn[idx] = sn;
    }
}

// Leaf level: h = (1 - sigmoid(x.wiz + bz)) * tanh(x.win + bn) * mask
__global__ void __launch_bounds__(256)
leaf_kernel(const float* __restrict__ x,
            const float* __restrict__ wiz, const float* __restrict__ wiz_b, const float* __restrict__ whz_b,
            const float* __restrict__ win, const float* __restrict__ win_b, const float* __restrict__ whn_b,
            const float* __restrict__ maskp, float* __restrict__ outp)
{
    const int o = threadIdx.x;
    float wz[32], wn[32];
#pragma unroll
    for (int i = 0; i < 32; i++) { wz[i] = wiz[o * 32 + i]; wn[i] = win[o * 32 + i]; }
    const float bz = wiz_b[o] + whz_b[o];
    const float bn = win_b[o] + whn_b[o];

    __shared__ float xs[32][33];
    __shared__ float ms[32];
    const long rowBase = (long)blockIdx.x * 32;
    {
        const int rr = threadIdx.x >> 3;
        const int cc = (threadIdx.x & 7) * 4;
        const float4 v = *(const float4*)(x + (rowBase + rr) * 32 + cc);
        xs[rr][cc] = v.x; xs[rr][cc + 1] = v.y; xs[rr][cc + 2] = v.z; xs[rr][cc + 3] = v.w;
    }
    if (threadIdx.x < 32) ms[threadIdx.x] = maskp[rowBase + threadIdx.x];
    __syncthreads();
    for (int rr = 0; rr < 32; rr++) {
        float sz = bz, sn = bn;
#pragma unroll
        for (int i = 0; i < 32; i++) {
            sz = fmaf(xs[rr][i], wz[i], sz);
            sn = fmaf(xs[rr][i], wn[i], sn);
        }
        const float zg = sigmoid_acc(sz);
        outp[(rowBase + rr) * 256 + o] = (1.0f - zg) * tanh_acc(sn) * ms[rr];
    }
}

// combine score partials: scores[k*R+row] = w_b + part[k][0][row] + part[k][1][row]
__global__ void combine_scores(const float* __restrict__ part, float* __restrict__ scores,
                               const float* __restrict__ wb, int R)
{
    const int i = blockIdx.x * 256 + threadIdx.x;
    if (i < 2 * R) {
        const int k = i / R, row = i - k * R;
        scores[i] = wb[0] + (part[(long)k * 2 * R + row] + part[(long)k * 2 * R + R + row]);
    }
}

// g = a0*c0 + a1*c1, a_k = scores_k / (scores_0 + scores_1). blockDim=64, grid=R
__global__ void __launch_bounds__(64)
g_kernel(const float* __restrict__ Hall, const float* __restrict__ scores,
         float* __restrict__ gp, int R, int start)
{
    const int row = blockIdx.x;
    const int jn = row >> 12, b = row & 4095;
    const long c0row = ((long)(2 * (start + jn) + 1) << 12) + b;
    const float s0 = scores[row], s1 = scores[R + row];
    const float inv = 1.0f / (s0 + s1);
    const float a0 = s0 * inv, a1 = s1 * inv;
    const int c = threadIdx.x * 4;
    const float4 c0 = *(const float4*)(Hall + c0row * 256 + c);
    const float4 c1 = *(const float4*)(Hall + (c0row + 4096) * 256 + c);
    float4 g;
    g.x = a0 * c0.x + a1 * c1.x;
    g.y = a0 * c0.y + a1 * c1.y;
    g.z = a0 * c0.z + a1 * c1.z;
    g.w = a0 * c0.w + a1 * c1.w;
    *(float4*)(gp + (long)row * 256 + c) = g;
}

extern "C" void kernel_launch(void* const* d_in, const int* in_sizes, int n_in,
                              void* d_out, int out_size)
{
    const float* targets = (const float*)d_in[0];
    const float* mask    = (const float*)d_in[1];
    const float* wir_w = (const float*)d_in[2];  const float* wir_b = (const float*)d_in[3];
    const float* whr_w = (const float*)d_in[4];  const float* whr_b = (const float*)d_in[5];
    const float* wiz_w = (const float*)d_in[6];  const float* wiz_b = (const float*)d_in[7];
    const float* whz_w = (const float*)d_in[8];  const float* whz_b = (const float*)d_in[9];
    const float* win_w = (const float*)d_in[10]; const float* win_b = (const float*)d_in[11];
    const float* whn_w = (const float*)d_in[12]; const float* whn_b = (const float*)d_in[13];
    const float* wms_w = (const float*)d_in[14]; const float* wms_b = (const float*)d_in[15];
    const float* w_w   = (const float*)d_in[16]; const float* w_b   = (const float*)d_in[17];
    const float* wa_w  = (const float*)d_in[18]; const float* wa_b  = (const float*)d_in[19];
    const float* mu_w  = (const float*)d_in[20]; const float* mu_b  = (const float*)d_in[21];
    const float* lv_w  = (const float*)d_in[22]; const float* lv_b  = (const float*)d_in[23];
    float* outp = (float*)d_out;

    float *Hall, *g, *cs, *xir, *xiz, *xin, *scores, *spart;
    cudaGetSymbolAddress((void**)&Hall,   d_Hall);
    cudaGetSymbolAddress((void**)&g,      d_g);
    cudaGetSymbolAddress((void**)&cs,     d_cs);
    cudaGetSymbolAddress((void**)&xir,    d_xir);
    cudaGetSymbolAddress((void**)&xiz,    d_xiz);
    cudaGetSymbolAddress((void**)&xin,    d_xin);
    cudaGetSymbolAddress((void**)&scores, d_scores);
    cudaGetSymbolAddress((void**)&spart,  d_spart);

    // ---- Leaf level: d = 6, start = 63, n = 64 ----
    {
        const long start = 63;
        leaf_kernel<<<(64 * BATCH) / 32, 256>>>(
            targets + start * BATCH * IDIM,
            wiz_w, wiz_b, whz_b, win_w, win_b, whn_b,
            mask + start * BATCH,
            Hall + start * BATCH * HDIM);
    }

    // ---- Internal levels d = 5 .. 0 ----
    for (int d = 5; d >= 0; d--) {
        const int start = (1 << d) - 1;
        const int n = 1 << d;
        const int R = n * BATCH;
        const float* x = targets + (long)start * BATCH * IDIM;
        dim3 gg(R / 128, 2);

        // scores_k = w_b + sum_g tanh(c_k @ wms[k]^T + wms_b[k]) * w_w
        gemm256<M_SCORES><<<gg, 256>>>(Hall, wms_w,         wms_b,       nullptr, w_w, nullptr, nullptr, nullptr, spart,               start, 0);
        gemm256<M_SCORES><<<gg, 256>>>(Hall, wms_w + 65536, wms_b + 256, nullptr, w_w, nullptr, nullptr, nullptr, spart + (long)2 * R, start, 1);
        combine_scores<<<(2 * R + 255) / 256, 256>>>(spart, scores, w_b, R);

        // g = a0*c0 + a1*c1
        g_kernel<<<R, 64>>>(Hall, scores, g, R, start);

        // child_sum = tanh(g @ wa^T + wa_b)
        gemm256<M_TANHB><<<gg, 256>>>(g, wa_w, wa_b, cs, nullptr, nullptr, nullptr, nullptr, nullptr, start, 0);

        // xi precomputations (bias pairs folded), fused
        xi3_kernel<<<R / 32, 256>>>(x,
                                    wir_w, wir_b, whr_b,
                                    wiz_w, wiz_b, whz_b,
                                    win_w, win_b, whn_b,
                                    xir, xiz, xin);

        // z = sigmoid(xiz + child_sum @ whz^T)
        gemm256<M_Z><<<gg, 256>>>(cs, whz_w, nullptr, xiz, nullptr, nullptr, nullptr, nullptr, nullptr, start, 0);

        // s = sum_k sigmoid(xir + c_k @ whr^T) * c_k   (into g buffer)
        gemm256<M_R0><<<gg, 256>>>(Hall, whr_w, nullptr, g, xir, nullptr, nullptr, nullptr, nullptr, start, 0);
        gemm256<M_R1><<<gg, 256>>>(Hall, whr_w, nullptr, g, xir, nullptr, nullptr, nullptr, nullptr, start, 1);

        // n = tanh(xin + s @ whn^T); h = ((1-z)*n + z*cs) * mask -> Hall
        gemm256<M_FINAL><<<gg, 256>>>(g, whn_w, nullptr, Hall, xin, xiz, cs, mask, nullptr, start, 0);
    }

    // ---- Output heads ----
    dim3 go(BATCH / 128, 1);
    gemm256<M_OUT><<<go, 256>>>(Hall, mu_w, mu_b, outp,                     nullptr, nullptr, nullptr, nullptr, nullptr, 0, 0);
    gemm256<M_OUT><<<go, 256>>>(Hall, lv_w, lv_b, outp + (long)BATCH * 128, nullptr, nullptr, nullptr, nullptr, nullptr, 0, 0);
}

// round 17
// speedup vs baseline: 1.1277x; 1.0083x over previous
#include <cuda_runtime.h>
#include <math.h>

// Problem constants
#define BATCH 4096
#define HDIM  256
#define IDIM  32
#define NNODES 127
#define MAXR  (32 * BATCH)   // largest internal-level row count (d=5)

// ---------------- static device scratch ----------------
__device__ float d_Hall[(size_t)NNODES * BATCH * HDIM];
__device__ float d_g  [(size_t)MAXR * HDIM];
__device__ float d_cs [(size_t)MAXR * HDIM];
__device__ float d_xir[(size_t)MAXR * HDIM];
__device__ float d_xiz[(size_t)MAXR * HDIM];
__device__ float d_xin[(size_t)MAXR * HDIM];
__device__ float d_scores[2 * MAXR];
__device__ float d_spart[4 * MAXR];

// ---------------- accurate activations (immune to --use_fast_math) ----------
__device__ __forceinline__ float tanh_acc(float x) {
    const float ax = fabsf(x);
    if (ax < 0.25f) {
        const float x2 = x * x;
        float p = fmaf(x2, 0.021869488f, -0.053968254f);
        p = fmaf(x2, p, 0.13333334f);
        p = fmaf(x2, p, -0.33333334f);
        return fmaf(x2 * x, p, x);
    }
    const float t = __expf(2.0f * ax);
    const float r = 1.0f - 2.0f / (t + 1.0f);
    return copysignf(r, x);
}

__device__ __forceinline__ float sigmoid_acc(float x) {
    const float e = __expf(-fabsf(x));
    const float s = 1.0f / (1.0f + e);
    return x >= 0.0f ? s : e * s;
}

// packed f32x2 helpers (FFMA2)
typedef unsigned long long ull;
__device__ __forceinline__ ull dup2(float a) {
    ull r; asm("mov.b64 %0, {%1, %1};" : "=l"(r) : "f"(a)); return r;
}
__device__ __forceinline__ void fma2(ull& d, ull a, ull b) {
    asm("fma.rn.f32x2 %0, %1, %2, %0;" : "+l"(d) : "l"(a), "l"(b));
}
__device__ __forceinline__ float2 unpack2(ull v) {
    float lo, hi; asm("mov.b64 {%0, %1}, %2;" : "=f"(lo), "=f"(hi) : "l"(v));
    return make_float2(lo, hi);
}

// ---------------- GEMM modes ----------------
#define M_SCORES 0
#define M_TANHB  1
#define M_Z      2
#define M_R0     3
#define M_R1     4
#define M_FINAL  5
#define M_OUT    6

// Generic K=256 SGEMM (exact fp32, FFMA2 inner loop), tile 128x128x16,
// 256 threads, 8x8/thread.  ROT rotates k-chunk processing order
// (ROT=0 == proven R10 code bit-for-bit; ROT=8 is the reorder experiment).
template<int MODE, int ROT = 0>
__global__ void __launch_bounds__(256, 2)
gemm256(const float* __restrict__ A,
        const float* __restrict__ W,    // N x 256 row-major
        const float* __restrict__ bias,
        float* __restrict__ outp,
        const float* __restrict__ e0,
        const float* __restrict__ e1,
        const float* __restrict__ e2,
        const float* __restrict__ e3,
        float* __restrict__ eout,
        int start, int kchild)
{
    __shared__ __align__(16) float As[16][132];
    __shared__ __align__(16) float Bs[16][132];

    const int tid = threadIdx.x;
    const int rowBase = blockIdx.x * 128;
    const int colBase = blockIdx.y * 128;

    const int r  = tid >> 1;
    const int kq = (tid & 1) * 4;
    const int row_g = rowBase + r;

    long arow;
    if (MODE == M_SCORES || MODE == M_R0 || MODE == M_R1) {
        const int jn = row_g >> 12;
        const int b  = row_g & 4095;
        arow = ((long)(2 * (start + jn) + 1 + kchild) << 12) + b;
    } else {
        arow = row_g;
    }
    const float* Ap = A + arow * 256 + kq;
    const float* Wp = W + (long)(colBase + r) * 256 + kq;

    ull acc[8][4];
#pragma unroll
    for (int i = 0; i < 8; i++)
#pragma unroll
        for (int jp = 0; jp < 4; jp++) acc[i][jp] = 0ull;

    const int ty = tid >> 4;
    const int tx = tid & 15;

    // prefetch first tile (chunk ROT)
    float4 av0 = *(const float4*)(Ap + ROT * 16);
    float4 av1 = *(const float4*)(Ap + ROT * 16 + 8);
    float4 wv0 = *(const float4*)(Wp + ROT * 16);
    float4 wv1 = *(const float4*)(Wp + ROT * 16 + 8);

    for (int it = 0; it < 16; it++) {
        __syncthreads();
        As[kq + 0][r] = av0.x; As[kq + 1][r] = av0.y; As[kq + 2][r] = av0.z; As[kq + 3][r] = av0.w;
        As[kq + 8][r] = av1.x; As[kq + 9][r] = av1.y; As[kq + 10][r] = av1.z; As[kq + 11][r] = av1.w;
        Bs[kq + 0][r] = wv0.x; Bs[kq + 1][r] = wv0.y; Bs[kq + 2][r] = wv0.z; Bs[kq + 3][r] = wv0.w;
        Bs[kq + 8][r] = wv1.x; Bs[kq + 9][r] = wv1.y; Bs[kq + 10][r] = wv1.z; Bs[kq + 11][r] = wv1.w;
        __syncthreads();
        if (it < 15) {
            const int koff = ((it + 1 + ROT) & 15) * 16;
            av0 = *(const float4*)(Ap + koff);
            av1 = *(const float4*)(Ap + koff + 8);
            wv0 = *(const float4*)(Wp + koff);
            wv1 = *(const float4*)(Wp + koff + 8);
        }
#pragma unroll
        for (int kk = 0; kk < 16; kk++) {
            const ulonglong2 b01 = *(const ulonglong2*)&Bs[kk][tx * 8];
            const ulonglong2 b23 = *(const ulonglong2*)&Bs[kk][tx * 8 + 4];
#pragma unroll
            for (int i = 0; i < 8; i++) {
                const ull ad = dup2(As[kk][ty * 8 + i]);
                fma2(acc[i][0], ad, b01.x);
                fma2(acc[i][1], ad, b01.y);
                fma2(acc[i][2], ad, b23.x);
                fma2(acc[i][3], ad, b23.y);
            }
        }
    }

    if (MODE == M_SCORES) {
        const long R = (long)gridDim.x * 128;
#pragma unroll
        for (int i = 0; i < 8; i++) {
            float p = 0.0f;
#pragma unroll
            for (int jp = 0; jp < 4; jp++) {
                const float2 v = unpack2(acc[i][jp]);
                const int col = colBase + tx * 8 + 2 * jp;
                p += tanh_acc(v.x + bias[col])     * e0[col];
                p += tanh_acc(v.y + bias[col + 1]) * e0[col + 1];
            }
            p += __shfl_xor_sync(0xffffffffu, p, 8);
            p += __shfl_xor_sync(0xffffffffu, p, 4);
            p += __shfl_xor_sync(0xffffffffu, p, 2);
            p += __shfl_xor_sync(0xffffffffu, p, 1);
            if (tx == 0)
                eout[(long)blockIdx.y * R + rowBase + ty * 8 + i] = p;
        }
        return;
    }

#pragma unroll
    for (int i = 0; i < 8; i++) {
        const int row = rowBase + ty * 8 + i;
#pragma unroll
        for (int jp = 0; jp < 4; jp++) {
            const float2 vv = unpack2(acc[i][jp]);
#pragma unroll
            for (int h = 0; h < 2; h++) {
                const int col = colBase + tx * 8 + 2 * jp + h;
                const long idx = (long)row * 256 + col;
                const float v = h ? vv.y : vv.x;
                if (MODE == M_TANHB) {
                    outp[idx] = tanh_acc(v + bias[col]);
                } else if (MODE == M_Z) {
                    outp[idx] = sigmoid_acc(v + outp[idx]);
                } else if (MODE == M_R0 || MODE == M_R1) {
                    const int jn = row >> 12, b = row & 4095;
                    const long crow = ((long)(2 * (start + jn) + 1 + kchild) << 12) + b;
                    const float c = A[crow * 256 + col];
                    float val = sigmoid_acc(v + e0[idx]) * c;
                    if (MODE == M_R1) val += outp[idx];
                    outp[idx] = val;
                } else if (MODE == M_FINAL) {
                    const float nv = tanh_acc(v + e0[idx]);
                    const float z  = e1[idx];
                    const float hs = e2[idx];
                    const int jn = row >> 12, b = row & 4095;
                    const float m = e3[(long)(start + jn) * BATCH + b];
                    outp[((long)start * BATCH + row) * 256 + col] = ((1.0f - z) * nv + z * hs) * m;
                } else if (MODE == M_OUT) {
                    outp[(long)row * 128 + col] = v + bias[col];
                }
            }
        }
    }
}

// fused xi kernel: all three K=32 input projections in one pass
__global__ void __launch_bounds__(256)
xi3_kernel(const float* __restrict__ x,
           const float* __restrict__ Wr, const float* __restrict__ br1, const float* __restrict__ br2,
           const float* __restrict__ Wz, const float* __restrict__ bz1, const float* __restrict__ bz2,
           const float* __restrict__ Wn, const float* __restrict__ bn1, const float* __restrict__ bn2,
           float* __restrict__ outr, float* __restrict__ outz, float* __restrict__ outn)
{
    const int o = threadIdx.x;
    float wr[32], wz[32], wn[32];
#pragma unroll
    for (int i = 0; i < 32; i++) {
        wr[i] = Wr[o * 32 + i];
        wz[i] = Wz[o * 32 + i];
        wn[i] = Wn[o * 32 + i];
    }
    const float biasr = br1[o] + br2[o];
    const float biasz = bz1[o] + bz2[o];
    const float biasn = bn1[o] + bn2[o];

    __shared__ float xs[32][33];
    const long rowBase = (long)blockIdx.x * 32;
    {
        const int rr = threadIdx.x >> 3;
        const int cc = (threadIdx.x & 7) * 4;
        const float4 v = *(const float4*)(x + (rowBase + rr) * 32 + cc);
        xs[rr][cc] = v.x; xs[rr][cc + 1] = v.y; xs[rr][cc + 2] = v.z; xs[rr][cc + 3] = v.w;
    }
    __syncthreads();
    for (int rr = 0; rr < 32; rr++) {
        float sr = biasr, sz = biasz, sn = biasn;
#pragma unroll
        for (int i = 0; i < 32; i++) {
            const float xv = xs[rr][i];
            sr = fmaf(xv, wr[i], sr);
            sz = fmaf(xv, wz[i], sz);
            sn = fmaf(xv, wn[i], sn);
        }
        const long idx = (rowBase + rr) * 256 + o;
        outr[idx] = sr;
        outz[idx] = sz;
        outn[idx] = sn;
    }
}

// Leaf level
__global__ void __launch_bounds__(256)
leaf_kernel(const float* __restrict__ x,
            const float* __restrict__ wiz, const float* __restrict__ wiz_b, const float* __restrict__ whz_b,
            const float* __restrict__ win, const float* __restrict__ win_b, const float* __restrict__ whn_b,
            const float* __restrict__ maskp, float* __restrict__ outp)
{
    const int o = threadIdx.x;
    float wz[32], wn[32];
#pragma unroll
    for (int i = 0; i < 32; i++) { wz[i] = wiz[o * 32 + i]; wn[i] = win[o * 32 + i]; }
    const float bz = wiz_b[o] + whz_b[o];
    const float bn = win_b[o] + whn_b[o];

    __shared__ float xs[32][33];
    __shared__ float ms[32];
    const long rowBase = (long)blockIdx.x * 32;
    {
        const int rr = threadIdx.x >> 3;
        const int cc = (threadIdx.x & 7) * 4;
        const float4 v = *(const float4*)(x + (rowBase + rr) * 32 + cc);
        xs[rr][cc] = v.x; xs[rr][cc + 1] = v.y; xs[rr][cc + 2] = v.z; xs[rr][cc + 3] = v.w;
    }
    if (threadIdx.x < 32) ms[threadIdx.x] = maskp[rowBase + threadIdx.x];
    __syncthreads();
    for (int rr = 0; rr < 32; rr++) {
        float sz = bz, sn = bn;
#pragma unroll
        for (int i = 0; i < 32; i++) {
            sz = fmaf(xs[rr][i], wz[i], sz);
            sn = fmaf(xs[rr][i], wn[i], sn);
        }
        const float zg = sigmoid_acc(sz);
        outp[(rowBase + rr) * 256 + o] = (1.0f - zg) * tanh_acc(sn) * ms[rr];
    }
}

// combine score partials
__global__ void combine_scores(const float* __restrict__ part, float* __restrict__ scores,
                               const float* __restrict__ wb, int R)
{
    const int i = blockIdx.x * 256 + threadIdx.x;
    if (i < 2 * R) {
        const int k = i / R, row = i - k * R;
        scores[i] = wb[0] + (part[(long)k * 2 * R + row] + part[(long)k * 2 * R + R + row]);
    }
}

// g = a0*c0 + a1*c1
__global__ void __launch_bounds__(64)
g_kernel(const float* __restrict__ Hall, const float* __restrict__ scores,
         float* __restrict__ gp, int R, int start)
{
    const int row = blockIdx.x;
    const int jn = row >> 12, b = row & 4095;
    const long c0row = ((long)(2 * (start + jn) + 1) << 12) + b;
    const float s0 = scores[row], s1 = scores[R + row];
    const float inv = 1.0f / (s0 + s1);
    const float a0 = s0 * inv, a1 = s1 * inv;
    const int c = threadIdx.x * 4;
    const float4 c0 = *(const float4*)(Hall + c0row * 256 + c);
    const float4 c1 = *(const float4*)(Hall + (c0row + 4096) * 256 + c);
    float4 g;
    g.x = a0 * c0.x + a1 * c1.x;
    g.y = a0 * c0.y + a1 * c1.y;
    g.z = a0 * c0.z + a1 * c1.z;
    g.w = a0 * c0.w + a1 * c1.w;
    *(float4*)(gp + (long)row * 256 + c) = g;
}

extern "C" void kernel_launch(void* const* d_in, const int* in_sizes, int n_in,
                              void* d_out, int out_size)
{
    const float* targets = (const float*)d_in[0];
    const float* mask    = (const float*)d_in[1];
    const float* wir_w = (const float*)d_in[2];  const float* wir_b = (const float*)d_in[3];
    const float* whr_w = (const float*)d_in[4];  const float* whr_b = (const float*)d_in[5];
    const float* wiz_w = (const float*)d_in[6];  const float* wiz_b = (const float*)d_in[7];
    const float* whz_w = (const float*)d_in[8];  const float* whz_b = (const float*)d_in[9];
    const float* win_w = (const float*)d_in[10]; const float* win_b = (const float*)d_in[11];
    const float* whn_w = (const float*)d_in[12]; const float* whn_b = (const float*)d_in[13];
    const float* wms_w = (const float*)d_in[14]; const float* wms_b = (const float*)d_in[15];
    const float* w_w   = (const float*)d_in[16]; const float* w_b   = (const float*)d_in[17];
    const float* wa_w  = (const float*)d_in[18]; const float* wa_b  = (const float*)d_in[19];
    const float* mu_w  = (const float*)d_in[20]; const float* mu_b  = (const float*)d_in[21];
    const float* lv_w  = (const float*)d_in[22]; const float* lv_b  = (const float*)d_in[23];
    float* outp = (float*)d_out;

    float *Hall, *g, *cs, *xir, *xiz, *xin, *scores, *spart;
    cudaGetSymbolAddress((void**)&Hall,   d_Hall);
    cudaGetSymbolAddress((void**)&g,      d_g);
    cudaGetSymbolAddress((void**)&cs,     d_cs);
    cudaGetSymbolAddress((void**)&xir,    d_xir);
    cudaGetSymbolAddress((void**)&xiz,    d_xiz);
    cudaGetSymbolAddress((void**)&xin,    d_xin);
    cudaGetSymbolAddress((void**)&scores, d_scores);
    cudaGetSymbolAddress((void**)&spart,  d_spart);

    // ---- Leaf level ----
    {
        const long start = 63;
        leaf_kernel<<<(64 * BATCH) / 32, 256>>>(
            targets + start * BATCH * IDIM,
            wiz_w, wiz_b, whz_b, win_w, win_b, whn_b,
            mask + start * BATCH,
            Hall + start * BATCH * HDIM);
    }

    // ---- Internal levels d = 5 .. 0 ----
    for (int d = 5; d >= 0; d--) {
        const int start = (1 << d) - 1;
        const int n = 1 << d;
        const int R = n * BATCH;
        const float* x = targets + (long)start * BATCH * IDIM;
        dim3 gg(R / 128, 2);

        // scores (bit-identical R10 path, ROT=0)
        gemm256<M_SCORES><<<gg, 256>>>(Hall, wms_w,         wms_b,       nullptr, w_w, nullptr, nullptr, nullptr, spart,               start, 0);
        gemm256<M_SCORES><<<gg, 256>>>(Hall, wms_w + 65536, wms_b + 256, nullptr, w_w, nullptr, nullptr, nullptr, spart + (long)2 * R, start, 1);
        combine_scores<<<(2 * R + 255) / 256, 256>>>(spart, scores, w_b, R);
        g_kernel<<<R, 64>>>(Hall, scores, g, R, start);

        // child_sum = tanh(g @ wa^T + wa_b)  --- EXPERIMENT: rotated k-chunk order ---
        gemm256<M_TANHB, 8><<<gg, 256>>>(g, wa_w, wa_b, cs, nullptr, nullptr, nullptr, nullptr, nullptr, start, 0);

        xi3_kernel<<<R / 32, 256>>>(x,
                                    wir_w, wir_b, whr_b,
                                    wiz_w, wiz_b, whz_b,
                                    win_w, win_b, whn_b,
                                    xir, xiz, xin);

        // z = sigmoid(xiz + cs @ whz^T)   (ROT=0)
        gemm256<M_Z><<<gg, 256>>>(cs, whz_w, nullptr, xiz, nullptr, nullptr, nullptr, nullptr, nullptr, start, 0);

        // s = sum_k sigmoid(xir + c_k @ whr^T) * c_k   (ROT=0)
        gemm256<M_R0><<<gg, 256>>>(Hall, whr_w, nullptr, g, xir, nullptr, nullptr, nullptr, nullptr, start, 0);
        gemm256<M_R1><<<gg, 256>>>(Hall, whr_w, nullptr, g, xir, nullptr, nullptr, nullptr, nullptr, start, 1);

        // h = ((1-z)*tanh(xin + s @ whn^T) + z*cs) * mask   (ROT=0)
        gemm256<M_FINAL><<<gg, 256>>>(g, whn_w, nullptr, Hall, xin, xiz, cs, mask, nullptr, start, 0);
    }

    // ---- Output heads (ROT=0) ----
    dim3 go(BATCH / 128, 1);
    gemm256<M_OUT><<<go, 256>>>(Hall, mu_w, mu_b, outp,                     nullptr, nullptr, nullptr, nullptr, nullptr, 0, 0);
    gemm256<M_OUT><<<go, 256>>>(Hall, lv_w, lv_b, outp + (long)BATCH * 128, nullptr, nullptr, nullptr, nullptr, nullptr, 0, 0);
}